// round 8
// baseline (speedup 1.0000x reference)
#include <cuda_runtime.h>
#include <cuda_bf16.h>
#include <cstdint>

#define M_MATCH 5000
#define TOT     10000
#define CF      128
#define CC      256
#define WW      25
#define LCELLS  4800
#define HFD     240
#define WFD     320
#define CHW     (CF * HFD * WFD)

typedef unsigned long long ull;

__device__ float g_t[TOT * CF];
__device__ float g_Wc[CC * CF];
__device__ float g_bc[CF];

__device__ __forceinline__ uint32_t smem_u32(const void* p) {
    uint32_t a;
    asm("{ .reg .u64 t; cvta.to.shared.u64 t, %1; cvt.u32.u64 %0, t; }" : "=r"(a) : "l"(p));
    return a;
}

#define LDSM_X4(r0, r1, r2, r3, addr)                                          \
    asm volatile("ldmatrix.sync.aligned.m8n8.x4.shared.b16 {%0,%1,%2,%3}, [%4];" \
        : "=r"(r0), "=r"(r1), "=r"(r2), "=r"(r3) : "r"(addr))

#define MMA16816(d, a0, a1, a2, a3, b0, b1)                                    \
    asm volatile("mma.sync.aligned.m16n8k16.row.col.f32.bf16.bf16.f32 "        \
        "{%0,%1,%2,%3}, {%4,%5,%6,%7}, {%8,%9}, {%0,%1,%2,%3};"                \
        : "+f"((d)[0]), "+f"((d)[1]), "+f"((d)[2]), "+f"((d)[3])               \
        : "r"(a0), "r"(a1), "r"(a2), "r"(a3), "r"(b0), "r"(b1))

#define CP_ASYNC4(dst, src, sz)                                                \
    asm volatile("cp.async.ca.shared.global [%0], [%1], 4, %2;"                \
        :: "r"(dst), "l"(src), "r"(sz) : "memory")
#define CP_COMMIT() asm volatile("cp.async.commit_group;" ::: "memory")
#define CP_WAIT0()  asm volatile("cp.async.wait_group 0;" ::: "memory")

__global__ void warmup_kernel() {}

// ---------------------------------------------------------------------------
// Kernel 0: Wc[c][o] = sum_j Wd[j][c]*W2[o][j];  bc = W2@bd + bm
// ---------------------------------------------------------------------------
__global__ void __launch_bounds__(128)
wc_kernel(const float* __restrict__ Wd, const float* __restrict__ bd,
          const float* __restrict__ Wm, const float* __restrict__ bm)
{
    extern __shared__ float w2T[];   // [j][129]
    const int tid = threadIdx.x;
    const int c = blockIdx.x;

    for (int it = 0; it < 128; it++)
        w2T[tid * 129 + it] = Wm[it * 256 + 128 + tid];   // w2T[j=tid][o=it]
    __syncthreads();

    float a0 = 0.f, a1 = 0.f;
    #pragma unroll 4
    for (int j = 0; j < 128; j++) {
        float w2 = w2T[j * 129 + tid];
        a0 += __ldg(&Wd[j * 256 + c])       * w2;
        a1 += __ldg(&Wd[j * 256 + c + 128]) * w2;
    }
    g_Wc[(size_t)c * 128 + tid]         = a0;
    g_Wc[(size_t)(c + 128) * 128 + tid] = a1;

    if (blockIdx.x == 0) {
        float acc = bm[tid];
        #pragma unroll 4
        for (int j = 0; j < 128; j++)
            acc += w2T[j * 129 + tid] * __ldg(&bd[j]);
        g_bc[tid] = acc;
    }
}

// ---------------------------------------------------------------------------
// Kernel 1: t = gather(feat_c) @ Wc + bc.  32-row tiles, 313 blocks, occ 2.
// ---------------------------------------------------------------------------
#define PTILE 32
#define NPTILES ((TOT + PTILE - 1) / PTILE)   // 313

__global__ void __launch_bounds__(256, 2)
proj_kernel(const float* __restrict__ feat_c0, const float* __restrict__ feat_c1,
            const int* __restrict__ b_ids, const int* __restrict__ i_ids,
            const int* __restrict__ j_ids)
{
    extern __shared__ char sraw[];
    float* A   = (float*)sraw;                       // [32][64]  8 KB
    float* Wcs = (float*)(sraw + 8192);              // [64][128] 32 KB
    const float** srow = (const float**)(sraw + 8192 + 32768);

    const int tid = threadIdx.x;
    const int tile = blockIdx.x;
    const int og = tid & 15, rg = tid >> 4;
    const int o0 = og * 8;

    if (tid < PTILE) {
        int m = tile * PTILE + tid;
        const float* p = nullptr;
        if (m < TOT) {
            int mm = (m < M_MATCH) ? m : m - M_MATCH;
            int b  = b_ids[mm];
            int l  = (m < M_MATCH) ? i_ids[mm] : j_ids[mm];
            p = ((m < M_MATCH) ? feat_c0 : feat_c1) + ((size_t)b * LCELLS + l) * CC;
        }
        srow[tid] = p;
    }

    float acc[2][8];
    {
        float4 bA = *(const float4*)&g_bc[o0];
        float4 bB = *(const float4*)&g_bc[o0 + 4];
        #pragma unroll
        for (int j = 0; j < 2; j++) {
            acc[j][0] = bA.x; acc[j][1] = bA.y; acc[j][2] = bA.z; acc[j][3] = bA.w;
            acc[j][4] = bB.x; acc[j][5] = bB.y; acc[j][6] = bB.z; acc[j][7] = bB.w;
        }
    }
    __syncthreads();

    for (int kc = 0; kc < 256; kc += 64) {
        for (int e = tid; e < 32 * 64; e += 256) {
            const float* p = srow[e >> 6];
            A[e] = p ? __ldg(p + kc + (e & 63)) : 0.f;
        }
        for (int e = tid; e < 64 * 128; e += 256)
            Wcs[e] = g_Wc[(size_t)(kc + (e >> 7)) * 128 + (e & 127)];
        __syncthreads();

        #pragma unroll 2
        for (int k = 0; k < 64; k += 4) {
            float4 fv[2];
            #pragma unroll
            for (int j = 0; j < 2; j++)
                fv[j] = *(const float4*)&A[(rg + 16 * j) * 64 + k];
            #define PSTEP(kk, COMP)                                            \
            {                                                                  \
                float4 wA = *(const float4*)&Wcs[(k + kk) * 128 + o0];         \
                float4 wB = *(const float4*)&Wcs[(k + kk) * 128 + o0 + 4];     \
                _Pragma("unroll")                                              \
                for (int j = 0; j < 2; j++) {                                  \
                    float a = fv[j].COMP;                                      \
                    acc[j][0] += a * wA.x; acc[j][1] += a * wA.y;              \
                    acc[j][2] += a * wA.z; acc[j][3] += a * wA.w;              \
                    acc[j][4] += a * wB.x; acc[j][5] += a * wB.y;              \
                    acc[j][6] += a * wB.z; acc[j][7] += a * wB.w;              \
                }                                                              \
            }
            PSTEP(0, x) PSTEP(1, y) PSTEP(2, z) PSTEP(3, w)
            #undef PSTEP
        }
        __syncthreads();
    }

    #pragma unroll
    for (int j = 0; j < 2; j++) {
        int m = tile * PTILE + rg + 16 * j;
        if (m < TOT) {
            float* dst = &g_t[(size_t)m * CF + o0];
            *(float4*)dst       = make_float4(acc[j][0], acc[j][1], acc[j][2], acc[j][3]);
            *(float4*)(dst + 4) = make_float4(acc[j][4], acc[j][5], acc[j][6], acc[j][7]);
        }
    }
}

// ---------------------------------------------------------------------------
// Kernel 2: fine — incremental-decode cp.async gather + pipeline + HMMA.
// ---------------------------------------------------------------------------
#define APITCH   136
#define ABYTES   (128 * APITCH * 2)
#define OFF_AH   0
#define OFF_AL   34816
#define OFF_BH   69632
#define OFF_BL   104448
#define OFF_STG  139264                   // 16384 f32
#define OFF_TS   204800                   // 2 x 640 f32
#define OFF_NSFB 209920
#define OFF_NSL  209960
#define SMEM_FINE 210048

__device__ __forceinline__ void decode_flat(unsigned flat, int& pos, int& p80,
                                            int& row, int& col, int& off)
{
    unsigned ch = flat / 120000u;
    unsigned r1 = flat - ch * 120000u;
    unsigned kk = r1 / 4800u;
    unsigned pp = r1 - kk * 4800u;
    int kh = (int)(kk / 5u);
    int kw = (int)(kk - 5u * (unsigned)kh);
    unsigned oh = pp / 80u;
    p80 = (int)(pp - 80u * oh);
    pos = (int)pp;
    row = (int)oh * 4 + kh - 2;
    col = p80 * 4 + kw - 2;
    off = (int)ch * 76800 + row * 320 + col;
}

// gather one tile: 1024 items (128 rows x 8 blocks of 16 consecutive c)
__device__ __forceinline__ void issue_tile(
    uint32_t stg_sm, uint32_t tdst_sm,
    const int* nsl, const ull* nsfb, int nxt5, int tid)
{
    #pragma unroll
    for (int it = 0; it < 2; it++) {
        const int item = tid + (it << 9);
        const int r = item >> 3;
        uint32_t dst = stg_sm + (uint32_t)item * 64;
        if (r < 125) {
            const int mi = r / 25;
            const int w  = r - mi * 25;
            const float* fb = (const float*)nsfb[mi];
            unsigned flat = (unsigned)nsl[mi] * 3200u
                          + (unsigned)(w * 128 + (item & 7) * 16);
            int pos, p80, row, col, off;
            decode_flat(flat, pos, p80, row, col, off);
            #pragma unroll 4
            for (int q = 0; q < 16; q++) {
                const bool valid = ((row | col) >= 0);
                const float* src = valid ? (fb + off) : fb;
                CP_ASYNC4(dst, src, valid ? 4u : 0u);
                dst += 4;
                flat++; pos++; p80++; col += 4; off += 4;
                if (pos == 4800) {
                    decode_flat(flat, pos, p80, row, col, off);
                } else if (p80 == 80) {
                    p80 = 0; row += 4; col -= 320; off += 960;
                }
            }
        } else {
            const float* fb = (const float*)nsfb[0];
            #pragma unroll 4
            for (int q = 0; q < 16; q++) {
                CP_ASYNC4(dst, fb, 0u);
                dst += 4;
            }
        }
    }
    #pragma unroll
    for (int e2 = tid; e2 < 640; e2 += 512) {
        const float* src = &g_t[(size_t)(nxt5 + (e2 >> 7)) * CF + (e2 & 127)];
        CP_ASYNC4(tdst_sm + (uint32_t)e2 * 4, src, 4u);
    }
    CP_COMMIT();
}

__global__ void __launch_bounds__(512, 1)
fine_kernel(const float* __restrict__ feat_f0, const float* __restrict__ feat_f1,
            const int* __restrict__ b_ids, const int* __restrict__ i_ids,
            const int* __restrict__ j_ids,
            const float* __restrict__ Wm, float* __restrict__ out)
{
    extern __shared__ char sraw[];
    char* Ah = sraw + OFF_AH;
    char* Al = sraw + OFF_AL;
    char* Bh = sraw + OFF_BH;
    char* Bl = sraw + OFF_BL;
    float* stg = (float*)(sraw + OFF_STG);
    float* ts0 = (float*)(sraw + OFF_TS);
    ull*   nsfb = (ull*)(sraw + OFF_NSFB);
    int*   nsl  = (int*)(sraw + OFF_NSL);

    const uint32_t sAh = smem_u32(Ah);
    const uint32_t sAl = smem_u32(Al);
    const uint32_t sBh = smem_u32(Bh);
    const uint32_t sBl = smem_u32(Bl);
    const uint32_t sStg = smem_u32(stg);
    const uint32_t sTs  = smem_u32(ts0);

    const int tid  = threadIdx.x;
    const int wid  = tid >> 5;
    const int lane = tid & 31;
    const int grid = gridDim.x;

    // B prep (once): W1 = merge_w[:, :128], hi/lo split
    for (int e2 = tid; e2 < 8192; e2 += 512) {
        int o = e2 >> 6;
        int c = (e2 & 63) * 2;
        float v0 = Wm[o * 256 + c];
        float v1 = Wm[o * 256 + c + 1];
        __nv_bfloat16 h0 = __float2bfloat16(v0);
        __nv_bfloat16 h1 = __float2bfloat16(v1);
        __nv_bfloat16 l0 = __float2bfloat16(v0 - __bfloat162float(h0));
        __nv_bfloat16 l1 = __float2bfloat16(v1 - __bfloat162float(h1));
        __nv_bfloat162 hp, lp; hp.x = h0; hp.y = h1; lp.x = l0; lp.y = l1;
        *(uint32_t*)(Bh + o * 272 + c * 2) = *(uint32_t*)&hp;
        *(uint32_t*)(Bl + o * 272 + c * 2) = *(uint32_t*)&lp;
    }

    const int mbase = (wid & 3) * 32;
    const int nbase = (wid >> 2) * 32;
    const uint32_t aRow  = (uint32_t)(mbase + (lane & 15));
    const uint32_t aColB = (uint32_t)((lane >> 4) * 16);
    const uint32_t bRow  = (uint32_t)(nbase + (lane & 7) + ((lane >> 4) << 3));
    const uint32_t bColB = (uint32_t)(((lane >> 3) & 1) * 16);

    // hoisted epilogue geometry (loop-invariant): 4 rows per thread
    const int rl = lane >> 2;
    const int cl = 2 * (lane & 3);
    int  rcst[4], rmi[4];
    bool rvld[4];
    #pragma unroll
    for (int jj = 0; jj < 4; jj++) {
        int r = mbase + 8 * jj + rl;
        rvld[jj] = (r < 125);
        int mi = r / 25;
        int w  = r - mi * 25;
        rmi[jj]  = mi;
        rcst[jj] = mi * 3200 + w * 128;
    }

    // prologue
    if (tid < 5) {
        int m  = (int)blockIdx.x * 5 + tid;
        int mm = (m < M_MATCH) ? m : m - M_MATCH;
        int b  = b_ids[mm];
        nsl[tid]  = (m < M_MATCH) ? i_ids[mm] : j_ids[mm];
        nsfb[tid] = (ull)(((m < M_MATCH) ? feat_f0 : feat_f1) + (size_t)b * CHW);
    }
    __syncthreads();
    issue_tile(sStg, sTs, nsl, nsfb, (int)blockIdx.x * 5, tid);

    int buf = 0;

    for (int tile = blockIdx.x; tile < 2000; tile += grid) {
        const int nxt = tile + grid;

        CP_WAIT0();
        __syncthreads();

        if (tid < 5 && nxt < 2000) {
            int m  = nxt * 5 + tid;
            int mm = (m < M_MATCH) ? m : m - M_MATCH;
            int b  = b_ids[mm];
            nsl[tid]  = (m < M_MATCH) ? i_ids[mm] : j_ids[mm];
            nsfb[tid] = (ull)(((m < M_MATCH) ? feat_f0 : feat_f1) + (size_t)b * CHW);
        }

        // convert stage -> Ah/Al via truncation + PRMT
        #pragma unroll 4
        for (int i = 0; i < 16; i++) {
            int e2 = tid + (i << 9);
            int r = e2 >> 6, cp = e2 & 63;
            uint2 u = *(const uint2*)&stg[r * 128 + cp * 2];
            uint32_t h0 = u.x & 0xFFFF0000u;
            uint32_t h1 = u.y & 0xFFFF0000u;
            float lo0 = __uint_as_float(u.x) - __uint_as_float(h0);
            float lo1 = __uint_as_float(u.y) - __uint_as_float(h1);
            uint32_t hp = __byte_perm(u.x, u.y, 0x7632);
            uint32_t lp = __byte_perm(__float_as_uint(lo0), __float_as_uint(lo1), 0x7632);
            *(uint32_t*)(Ah + r * 272 + cp * 4) = hp;
            *(uint32_t*)(Al + r * 272 + cp * 4) = lp;
        }
        __syncthreads();

        if (nxt < 2000)
            issue_tile(sStg, sTs + (uint32_t)(buf ^ 1) * 2560, nsl, nsfb, nxt * 5, tid);

        // ---- MMA: 3 terms x 8 k-steps ----
        float acc[2][4][4];
        #pragma unroll
        for (int i = 0; i < 2; i++)
            #pragma unroll
            for (int nb = 0; nb < 4; nb++) {
                acc[i][nb][0] = 0.f; acc[i][nb][1] = 0.f;
                acc[i][nb][2] = 0.f; acc[i][nb][3] = 0.f;
            }

        #pragma unroll 1
        for (int ks = 0; ks < 8; ks++) {
            const uint32_t kb = (uint32_t)(ks * 32);
            uint32_t a0_0, a0_1, a0_2, a0_3, a1_0, a1_1, a1_2, a1_3;
            uint32_t bfr[4][2];

            LDSM_X4(a0_0, a0_1, a0_2, a0_3, sAh + aRow * 272 + kb + aColB);
            LDSM_X4(a1_0, a1_1, a1_2, a1_3, sAh + (aRow + 16) * 272 + kb + aColB);
            #pragma unroll
            for (int bb = 0; bb < 2; bb++)
                LDSM_X4(bfr[2*bb][0], bfr[2*bb][1], bfr[2*bb+1][0], bfr[2*bb+1][1],
                        sBh + (bRow + bb * 16) * 272 + kb + bColB);
            #pragma unroll
            for (int nb = 0; nb < 4; nb++) {
                MMA16816(acc[0][nb], a0_0, a0_1, a0_2, a0_3, bfr[nb][0], bfr[nb][1]);
                MMA16816(acc[1][nb], a1_0, a1_1, a1_2, a1_3, bfr[nb][0], bfr[nb][1]);
            }
            #pragma unroll
            for (int bb = 0; bb < 2; bb++)
                LDSM_X4(bfr[2*bb][0], bfr[2*bb][1], bfr[2*bb+1][0], bfr[2*bb+1][1],
                        sBl + (bRow + bb * 16) * 272 + kb + bColB);
            #pragma unroll
            for (int nb = 0; nb < 4; nb++) {
                MMA16816(acc[0][nb], a0_0, a0_1, a0_2, a0_3, bfr[nb][0], bfr[nb][1]);
                MMA16816(acc[1][nb], a1_0, a1_1, a1_2, a1_3, bfr[nb][0], bfr[nb][1]);
            }
            LDSM_X4(a0_0, a0_1, a0_2, a0_3, sAl + aRow * 272 + kb + aColB);
            LDSM_X4(a1_0, a1_1, a1_2, a1_3, sAl + (aRow + 16) * 272 + kb + aColB);
            #pragma unroll
            for (int bb = 0; bb < 2; bb++)
                LDSM_X4(bfr[2*bb][0], bfr[2*bb][1], bfr[2*bb+1][0], bfr[2*bb+1][1],
                        sBh + (bRow + bb * 16) * 272 + kb + bColB);
            #pragma unroll
            for (int nb = 0; nb < 4; nb++) {
                MMA16816(acc[0][nb], a0_0, a0_1, a0_2, a0_3, bfr[nb][0], bfr[nb][1]);
                MMA16816(acc[1][nb], a1_0, a1_1, a1_2, a1_3, bfr[nb][0], bfr[nb][1]);
            }
        }

        // ---- epilogue ----
        {
            const float* tsp = ts0 + buf * 640;
            float* outb = out + (size_t)tile * 16000;
            #pragma unroll
            for (int i = 0; i < 2; i++) {
                const int j0 = 2 * i, j1 = 2 * i + 1;
                #pragma unroll
                for (int nb = 0; nb < 4; nb++) {
                    int col = nbase + nb * 8 + cl;
                    if (rvld[j0]) {
                        float2 o2;
                        o2.x = acc[i][nb][0] + tsp[rmi[j0] * 128 + col];
                        o2.y = acc[i][nb][1] + tsp[rmi[j0] * 128 + col + 1];
                        *(float2*)&outb[rcst[j0] + col] = o2;
                    }
                    if (rvld[j1]) {
                        float2 o2;
                        o2.x = acc[i][nb][2] + tsp[rmi[j1] * 128 + col];
                        o2.y = acc[i][nb][3] + tsp[rmi[j1] * 128 + col + 1];
                        *(float2*)&outb[rcst[j1] + col] = o2;
                    }
                }
            }
        }
        buf ^= 1;
        __syncthreads();
    }
}

// ---------------------------------------------------------------------------
extern "C" void kernel_launch(void* const* d_in, const int* in_sizes, int n_in,
                              void* d_out, int out_size)
{
    (void)in_sizes; (void)n_in; (void)out_size;
    const float* feat_f0 = (const float*)d_in[0];
    const float* feat_f1 = (const float*)d_in[1];
    const float* feat_c0 = (const float*)d_in[2];
    const float* feat_c1 = (const float*)d_in[3];
    const int*   b_ids   = (const int*)d_in[4];
    const int*   i_ids   = (const int*)d_in[5];
    const int*   j_ids   = (const int*)d_in[6];
    const float* Wd      = (const float*)d_in[7];
    const float* bd      = (const float*)d_in[8];
    const float* Wm      = (const float*)d_in[9];
    const float* bm      = (const float*)d_in[10];
    float* out = (float*)d_out;

    const size_t smemW = 128 * 129 * sizeof(float);
    const size_t smemP = 8192 + 32768 + PTILE * sizeof(float*);
    const size_t smemF = SMEM_FINE;

    cudaFuncSetAttribute(wc_kernel,   cudaFuncAttributeMaxDynamicSharedMemorySize, (int)smemW);
    cudaFuncSetAttribute(proj_kernel, cudaFuncAttributeMaxDynamicSharedMemorySize, (int)smemP);
    cudaFuncSetAttribute(fine_kernel, cudaFuncAttributeMaxDynamicSharedMemorySize, (int)smemF);

    warmup_kernel<<<1, 32>>>();
    wc_kernel<<<128, 128, smemW>>>(Wd, bd, Wm, bm);
    proj_kernel<<<NPTILES, 256, smemP>>>(feat_c0, feat_c1, b_ids, i_ids, j_ids);
    fine_kernel<<<148, 512, smemF>>>(feat_f0, feat_f1, b_ids, i_ids, j_ids, Wm, out);
}

// round 9
// speedup vs baseline: 1.9372x; 1.9372x over previous
#include <cuda_runtime.h>
#include <cuda_bf16.h>
#include <cstdint>

#define M_MATCH 5000
#define TOT     10000
#define CF      128
#define CC      256
#define WW      25
#define LCELLS  4800
#define HFD     240
#define WFD     320
#define CHW     (CF * HFD * WFD)

typedef unsigned long long ull;

__device__ float g_t[TOT * CF];
__device__ float g_Wc[CC * CF];
__device__ float g_bc[CF];

__device__ __forceinline__ uint32_t smem_u32(const void* p) {
    uint32_t a;
    asm("{ .reg .u64 t; cvta.to.shared.u64 t, %1; cvt.u32.u64 %0, t; }" : "=r"(a) : "l"(p));
    return a;
}

#define LDSM_X4(r0, r1, r2, r3, addr)                                          \
    asm volatile("ldmatrix.sync.aligned.m8n8.x4.shared.b16 {%0,%1,%2,%3}, [%4];" \
        : "=r"(r0), "=r"(r1), "=r"(r2), "=r"(r3) : "r"(addr))

#define MMA16816(d, a0, a1, a2, a3, b0, b1)                                    \
    asm volatile("mma.sync.aligned.m16n8k16.row.col.f32.bf16.bf16.f32 "        \
        "{%0,%1,%2,%3}, {%4,%5,%6,%7}, {%8,%9}, {%0,%1,%2,%3};"                \
        : "+f"((d)[0]), "+f"((d)[1]), "+f"((d)[2]), "+f"((d)[3])               \
        : "r"(a0), "r"(a1), "r"(a2), "r"(a3), "r"(b0), "r"(b1))

#define CP_ASYNC4(dst, src, sz)                                                \
    asm volatile("cp.async.ca.shared.global [%0], [%1], 4, %2;"                \
        :: "r"(dst), "l"(src), "r"(sz) : "memory")
#define CP_COMMIT() asm volatile("cp.async.commit_group;" ::: "memory")
#define CP_WAIT0()  asm volatile("cp.async.wait_group 0;" ::: "memory")

__global__ void warmup_kernel() {}

// ---------------------------------------------------------------------------
// Kernel 0: Wc[c][o] = sum_j Wd[j][c]*W2[o][j];  bc = W2@bd + bm
// ---------------------------------------------------------------------------
__global__ void __launch_bounds__(128)
wc_kernel(const float* __restrict__ Wd, const float* __restrict__ bd,
          const float* __restrict__ Wm, const float* __restrict__ bm)
{
    extern __shared__ float w2T[];   // [j][129]
    const int tid = threadIdx.x;
    const int c = blockIdx.x;

    for (int it = 0; it < 128; it++)
        w2T[tid * 129 + it] = Wm[it * 256 + 128 + tid];   // w2T[j=tid][o=it]
    __syncthreads();

    float a0 = 0.f, a1 = 0.f;
    #pragma unroll 4
    for (int j = 0; j < 128; j++) {
        float w2 = w2T[j * 129 + tid];
        a0 += __ldg(&Wd[j * 256 + c])       * w2;
        a1 += __ldg(&Wd[j * 256 + c + 128]) * w2;
    }
    g_Wc[(size_t)c * 128 + tid]         = a0;
    g_Wc[(size_t)(c + 128) * 128 + tid] = a1;

    if (blockIdx.x == 0) {
        float acc = bm[tid];
        #pragma unroll 4
        for (int j = 0; j < 128; j++)
            acc += w2T[j * 129 + tid] * __ldg(&bd[j]);
        g_bc[tid] = acc;
    }
}

// ---------------------------------------------------------------------------
// Kernel 1: t = gather(feat_c) @ Wc + bc.  32-row tiles, 313 blocks, occ 2.
// ---------------------------------------------------------------------------
#define PTILE 32
#define NPTILES ((TOT + PTILE - 1) / PTILE)   // 313

__global__ void __launch_bounds__(256, 2)
proj_kernel(const float* __restrict__ feat_c0, const float* __restrict__ feat_c1,
            const int* __restrict__ b_ids, const int* __restrict__ i_ids,
            const int* __restrict__ j_ids)
{
    extern __shared__ char sraw[];
    float* A   = (float*)sraw;                       // [32][64]  8 KB
    float* Wcs = (float*)(sraw + 8192);              // [64][128] 32 KB
    const float** srow = (const float**)(sraw + 8192 + 32768);

    const int tid = threadIdx.x;
    const int tile = blockIdx.x;
    const int og = tid & 15, rg = tid >> 4;
    const int o0 = og * 8;

    if (tid < PTILE) {
        int m = tile * PTILE + tid;
        const float* p = nullptr;
        if (m < TOT) {
            int mm = (m < M_MATCH) ? m : m - M_MATCH;
            int b  = b_ids[mm];
            int l  = (m < M_MATCH) ? i_ids[mm] : j_ids[mm];
            p = ((m < M_MATCH) ? feat_c0 : feat_c1) + ((size_t)b * LCELLS + l) * CC;
        }
        srow[tid] = p;
    }

    float acc[2][8];
    {
        float4 bA = *(const float4*)&g_bc[o0];
        float4 bB = *(const float4*)&g_bc[o0 + 4];
        #pragma unroll
        for (int j = 0; j < 2; j++) {
            acc[j][0] = bA.x; acc[j][1] = bA.y; acc[j][2] = bA.z; acc[j][3] = bA.w;
            acc[j][4] = bB.x; acc[j][5] = bB.y; acc[j][6] = bB.z; acc[j][7] = bB.w;
        }
    }
    __syncthreads();

    for (int kc = 0; kc < 256; kc += 64) {
        for (int e = tid; e < 32 * 64; e += 256) {
            const float* p = srow[e >> 6];
            A[e] = p ? __ldg(p + kc + (e & 63)) : 0.f;
        }
        for (int e = tid; e < 64 * 128; e += 256)
            Wcs[e] = g_Wc[(size_t)(kc + (e >> 7)) * 128 + (e & 127)];
        __syncthreads();

        #pragma unroll 2
        for (int k = 0; k < 64; k += 4) {
            float4 fv[2];
            #pragma unroll
            for (int j = 0; j < 2; j++)
                fv[j] = *(const float4*)&A[(rg + 16 * j) * 64 + k];
            #define PSTEP(kk, COMP)                                            \
            {                                                                  \
                float4 wA = *(const float4*)&Wcs[(k + kk) * 128 + o0];         \
                float4 wB = *(const float4*)&Wcs[(k + kk) * 128 + o0 + 4];     \
                _Pragma("unroll")                                              \
                for (int j = 0; j < 2; j++) {                                  \
                    float a = fv[j].COMP;                                      \
                    acc[j][0] += a * wA.x; acc[j][1] += a * wA.y;              \
                    acc[j][2] += a * wA.z; acc[j][3] += a * wA.w;              \
                    acc[j][4] += a * wB.x; acc[j][5] += a * wB.y;              \
                    acc[j][6] += a * wB.z; acc[j][7] += a * wB.w;              \
                }                                                              \
            }
            PSTEP(0, x) PSTEP(1, y) PSTEP(2, z) PSTEP(3, w)
            #undef PSTEP
        }
        __syncthreads();
    }

    #pragma unroll
    for (int j = 0; j < 2; j++) {
        int m = tile * PTILE + rg + 16 * j;
        if (m < TOT) {
            float* dst = &g_t[(size_t)m * CF + o0];
            *(float4*)dst       = make_float4(acc[j][0], acc[j][1], acc[j][2], acc[j][3]);
            *(float4*)(dst + 4) = make_float4(acc[j][4], acc[j][5], acc[j][6], acc[j][7]);
        }
    }
}

// ---------------------------------------------------------------------------
// Kernel 2: fine — coalesced + incremental-decode cp.async gather + HMMA.
// Warp owns 8 rows; lane L covers c = q*32+L (warp instr = 32 consecutive c,
// 4 cache lines); per-lane Δc=32 incremental decode.
// ---------------------------------------------------------------------------
#define APITCH   136
#define ABYTES   (128 * APITCH * 2)
#define OFF_AH   0
#define OFF_AL   34816
#define OFF_BH   69632
#define OFF_BL   104448
#define OFF_STG  139264                   // 16384 f32
#define OFF_TS   204800                   // 2 x 640 f32
#define OFF_NSFB 209920
#define OFF_NSL  209960
#define SMEM_FINE 210048

__device__ __forceinline__ void decode_flat(unsigned flat, int& pos, int& p80,
                                            int& row, int& col, int& off)
{
    unsigned ch = flat / 120000u;
    unsigned r1 = flat - ch * 120000u;
    unsigned kk = r1 / 4800u;
    unsigned pp = r1 - kk * 4800u;
    int kh = (int)(kk / 5u);
    int kw = (int)(kk - 5u * (unsigned)kh);
    unsigned oh = pp / 80u;
    p80 = (int)(pp - 80u * oh);
    pos = (int)pp;
    row = (int)oh * 4 + kh - 2;
    col = p80 * 4 + kw - 2;
    off = (int)ch * 76800 + row * 320 + col;
}

__device__ __forceinline__ void issue_tile(
    uint32_t stg_sm, uint32_t tdst_sm,
    const int* nsl, const ull* nsfb, int nxt5, int tid, int wid, int lane)
{
    #pragma unroll
    for (int rr = 0; rr < 8; rr++) {
        const int r = wid * 8 + rr;
        uint32_t dst = stg_sm + (uint32_t)(r * 128 + lane) * 4;
        if (r < 125) {
            const int mi = r / 25;
            const int w  = r - mi * 25;
            const float* fb = (const float*)nsfb[mi];
            unsigned flat = (unsigned)nsl[mi] * 3200u + (unsigned)(w * 128 + lane);
            int pos, p80, row, col, off;
            decode_flat(flat, pos, p80, row, col, off);
            #pragma unroll
            for (int q = 0; q < 4; q++) {
                const bool valid = ((row | col) >= 0);
                const float* src = valid ? (fb + off) : fb;
                CP_ASYNC4(dst, src, valid ? 4u : 0u);
                dst += 128;
                if (q < 3) {
                    flat += 32; pos += 32; p80 += 32; col += 128; off += 128;
                    if (pos >= 4800) {
                        decode_flat(flat, pos, p80, row, col, off);
                    } else if (p80 >= 80) {
                        p80 -= 80; row += 4; col -= 320; off += 960;
                    }
                }
            }
        } else {
            const float* fb = (const float*)nsfb[0];
            #pragma unroll
            for (int q = 0; q < 4; q++) {
                CP_ASYNC4(dst, fb, 0u);
                dst += 128;
            }
        }
    }
    #pragma unroll
    for (int e2 = tid; e2 < 640; e2 += 512) {
        const float* src = &g_t[(size_t)(nxt5 + (e2 >> 7)) * CF + (e2 & 127)];
        CP_ASYNC4(tdst_sm + (uint32_t)e2 * 4, src, 4u);
    }
    CP_COMMIT();
}

__global__ void __launch_bounds__(512, 1)
fine_kernel(const float* __restrict__ feat_f0, const float* __restrict__ feat_f1,
            const int* __restrict__ b_ids, const int* __restrict__ i_ids,
            const int* __restrict__ j_ids,
            const float* __restrict__ Wm, float* __restrict__ out)
{
    extern __shared__ char sraw[];
    char* Ah = sraw + OFF_AH;
    char* Al = sraw + OFF_AL;
    char* Bh = sraw + OFF_BH;
    char* Bl = sraw + OFF_BL;
    float* stg = (float*)(sraw + OFF_STG);
    float* ts0 = (float*)(sraw + OFF_TS);
    ull*   nsfb = (ull*)(sraw + OFF_NSFB);
    int*   nsl  = (int*)(sraw + OFF_NSL);

    const uint32_t sAh = smem_u32(Ah);
    const uint32_t sAl = smem_u32(Al);
    const uint32_t sBh = smem_u32(Bh);
    const uint32_t sBl = smem_u32(Bl);
    const uint32_t sStg = smem_u32(stg);
    const uint32_t sTs  = smem_u32(ts0);

    const int tid  = threadIdx.x;
    const int wid  = tid >> 5;
    const int lane = tid & 31;
    const int grid = gridDim.x;

    for (int e2 = tid; e2 < 8192; e2 += 512) {
        int o = e2 >> 6;
        int c = (e2 & 63) * 2;
        float v0 = Wm[o * 256 + c];
        float v1 = Wm[o * 256 + c + 1];
        __nv_bfloat16 h0 = __float2bfloat16(v0);
        __nv_bfloat16 h1 = __float2bfloat16(v1);
        __nv_bfloat16 l0 = __float2bfloat16(v0 - __bfloat162float(h0));
        __nv_bfloat16 l1 = __float2bfloat16(v1 - __bfloat162float(h1));
        __nv_bfloat162 hp, lp; hp.x = h0; hp.y = h1; lp.x = l0; lp.y = l1;
        *(uint32_t*)(Bh + o * 272 + c * 2) = *(uint32_t*)&hp;
        *(uint32_t*)(Bl + o * 272 + c * 2) = *(uint32_t*)&lp;
    }

    const int mbase = (wid & 3) * 32;
    const int nbase = (wid >> 2) * 32;
    const uint32_t aRow  = (uint32_t)(mbase + (lane & 15));
    const uint32_t aColB = (uint32_t)((lane >> 4) * 16);
    const uint32_t bRow  = (uint32_t)(nbase + (lane & 7) + ((lane >> 4) << 3));
    const uint32_t bColB = (uint32_t)(((lane >> 3) & 1) * 16);

    const int rl = lane >> 2;
    const int cl = 2 * (lane & 3);
    int  rcst[4], rmi[4];
    bool rvld[4];
    #pragma unroll
    for (int jj = 0; jj < 4; jj++) {
        int r = mbase + 8 * jj + rl;
        rvld[jj] = (r < 125);
        int mi = r / 25;
        int w  = r - mi * 25;
        rmi[jj]  = mi;
        rcst[jj] = mi * 3200 + w * 128;
    }

    if (tid < 5) {
        int m  = (int)blockIdx.x * 5 + tid;
        int mm = (m < M_MATCH) ? m : m - M_MATCH;
        int b  = b_ids[mm];
        nsl[tid]  = (m < M_MATCH) ? i_ids[mm] : j_ids[mm];
        nsfb[tid] = (ull)(((m < M_MATCH) ? feat_f0 : feat_f1) + (size_t)b * CHW);
    }
    __syncthreads();
    issue_tile(sStg, sTs, nsl, nsfb, (int)blockIdx.x * 5, tid, wid, lane);

    int buf = 0;

    for (int tile = blockIdx.x; tile < 2000; tile += grid) {
        const int nxt = tile + grid;

        CP_WAIT0();
        __syncthreads();

        if (tid < 5 && nxt < 2000) {
            int m  = nxt * 5 + tid;
            int mm = (m < M_MATCH) ? m : m - M_MATCH;
            int b  = b_ids[mm];
            nsl[tid]  = (m < M_MATCH) ? i_ids[mm] : j_ids[mm];
            nsfb[tid] = (ull)(((m < M_MATCH) ? feat_f0 : feat_f1) + (size_t)b * CHW);
        }

        // convert stage -> Ah/Al via truncation + PRMT
        #pragma unroll 4
        for (int i = 0; i < 16; i++) {
            int e2 = tid + (i << 9);
            int r = e2 >> 6, cp = e2 & 63;
            uint2 u = *(const uint2*)&stg[r * 128 + cp * 2];
            uint32_t h0 = u.x & 0xFFFF0000u;
            uint32_t h1 = u.y & 0xFFFF0000u;
            float lo0 = __uint_as_float(u.x) - __uint_as_float(h0);
            float lo1 = __uint_as_float(u.y) - __uint_as_float(h1);
            uint32_t hp = __byte_perm(u.x, u.y, 0x7632);
            uint32_t lp = __byte_perm(__float_as_uint(lo0), __float_as_uint(lo1), 0x7632);
            *(uint32_t*)(Ah + r * 272 + cp * 4) = hp;
            *(uint32_t*)(Al + r * 272 + cp * 4) = lp;
        }
        __syncthreads();

        if (nxt < 2000)
            issue_tile(sStg, sTs + (uint32_t)(buf ^ 1) * 2560, nsl, nsfb, nxt * 5,
                       tid, wid, lane);

        // ---- MMA: 3 terms x 8 k-steps ----
        float acc[2][4][4];
        #pragma unroll
        for (int i = 0; i < 2; i++)
            #pragma unroll
            for (int nb = 0; nb < 4; nb++) {
                acc[i][nb][0] = 0.f; acc[i][nb][1] = 0.f;
                acc[i][nb][2] = 0.f; acc[i][nb][3] = 0.f;
            }

        #pragma unroll 1
        for (int ks = 0; ks < 8; ks++) {
            const uint32_t kb = (uint32_t)(ks * 32);
            uint32_t a0_0, a0_1, a0_2, a0_3, a1_0, a1_1, a1_2, a1_3;
            uint32_t bfr[4][2];

            LDSM_X4(a0_0, a0_1, a0_2, a0_3, sAh + aRow * 272 + kb + aColB);
            LDSM_X4(a1_0, a1_1, a1_2, a1_3, sAh + (aRow + 16) * 272 + kb + aColB);
            #pragma unroll
            for (int bb = 0; bb < 2; bb++)
                LDSM_X4(bfr[2*bb][0], bfr[2*bb][1], bfr[2*bb+1][0], bfr[2*bb+1][1],
                        sBh + (bRow + bb * 16) * 272 + kb + bColB);
            #pragma unroll
            for (int nb = 0; nb < 4; nb++) {
                MMA16816(acc[0][nb], a0_0, a0_1, a0_2, a0_3, bfr[nb][0], bfr[nb][1]);
                MMA16816(acc[1][nb], a1_0, a1_1, a1_2, a1_3, bfr[nb][0], bfr[nb][1]);
            }
            #pragma unroll
            for (int bb = 0; bb < 2; bb++)
                LDSM_X4(bfr[2*bb][0], bfr[2*bb][1], bfr[2*bb+1][0], bfr[2*bb+1][1],
                        sBl + (bRow + bb * 16) * 272 + kb + bColB);
            #pragma unroll
            for (int nb = 0; nb < 4; nb++) {
                MMA16816(acc[0][nb], a0_0, a0_1, a0_2, a0_3, bfr[nb][0], bfr[nb][1]);
                MMA16816(acc[1][nb], a1_0, a1_1, a1_2, a1_3, bfr[nb][0], bfr[nb][1]);
            }
            LDSM_X4(a0_0, a0_1, a0_2, a0_3, sAl + aRow * 272 + kb + aColB);
            LDSM_X4(a1_0, a1_1, a1_2, a1_3, sAl + (aRow + 16) * 272 + kb + aColB);
            #pragma unroll
            for (int bb = 0; bb < 2; bb++)
                LDSM_X4(bfr[2*bb][0], bfr[2*bb][1], bfr[2*bb+1][0], bfr[2*bb+1][1],
                        sBh + (bRow + bb * 16) * 272 + kb + bColB);
            #pragma unroll
            for (int nb = 0; nb < 4; nb++) {
                MMA16816(acc[0][nb], a0_0, a0_1, a0_2, a0_3, bfr[nb][0], bfr[nb][1]);
                MMA16816(acc[1][nb], a1_0, a1_1, a1_2, a1_3, bfr[nb][0], bfr[nb][1]);
            }
        }

        // ---- epilogue ----
        {
            const float* tsp = ts0 + buf * 640;
            float* outb = out + (size_t)tile * 16000;
            #pragma unroll
            for (int i = 0; i < 2; i++) {
                const int j0 = 2 * i, j1 = 2 * i + 1;
                #pragma unroll
                for (int nb = 0; nb < 4; nb++) {
                    int col = nbase + nb * 8 + cl;
                    if (rvld[j0]) {
                        float2 o2;
                        o2.x = acc[i][nb][0] + tsp[rmi[j0] * 128 + col];
                        o2.y = acc[i][nb][1] + tsp[rmi[j0] * 128 + col + 1];
                        *(float2*)&outb[rcst[j0] + col] = o2;
                    }
                    if (rvld[j1]) {
                        float2 o2;
                        o2.x = acc[i][nb][2] + tsp[rmi[j1] * 128 + col];
                        o2.y = acc[i][nb][3] + tsp[rmi[j1] * 128 + col + 1];
                        *(float2*)&outb[rcst[j1] + col] = o2;
                    }
                }
            }
        }
        buf ^= 1;
        __syncthreads();
    }
}

// ---------------------------------------------------------------------------
extern "C" void kernel_launch(void* const* d_in, const int* in_sizes, int n_in,
                              void* d_out, int out_size)
{
    (void)in_sizes; (void)n_in; (void)out_size;
    const float* feat_f0 = (const float*)d_in[0];
    const float* feat_f1 = (const float*)d_in[1];
    const float* feat_c0 = (const float*)d_in[2];
    const float* feat_c1 = (const float*)d_in[3];
    const int*   b_ids   = (const int*)d_in[4];
    const int*   i_ids   = (const int*)d_in[5];
    const int*   j_ids   = (const int*)d_in[6];
    const float* Wd      = (const float*)d_in[7];
    const float* bd      = (const float*)d_in[8];
    const float* Wm      = (const float*)d_in[9];
    const float* bm      = (const float*)d_in[10];
    float* out = (float*)d_out;

    const size_t smemW = 128 * 129 * sizeof(float);
    const size_t smemP = 8192 + 32768 + PTILE * sizeof(float*);
    const size_t smemF = SMEM_FINE;

    cudaFuncSetAttribute(wc_kernel,   cudaFuncAttributeMaxDynamicSharedMemorySize, (int)smemW);
    cudaFuncSetAttribute(proj_kernel, cudaFuncAttributeMaxDynamicSharedMemorySize, (int)smemP);
    cudaFuncSetAttribute(fine_kernel, cudaFuncAttributeMaxDynamicSharedMemorySize, (int)smemF);

    warmup_kernel<<<1, 32>>>();
    wc_kernel<<<128, 128, smemW>>>(Wd, bd, Wm, bm);
    proj_kernel<<<NPTILES, 256, smemP>>>(feat_c0, feat_c1, b_ids, i_ids, j_ids);
    fine_kernel<<<148, 512, smemF>>>(feat_f0, feat_f1, b_ids, i_ids, j_ids, Wm, out);
}

// round 10
// speedup vs baseline: 1.9384x; 1.0006x over previous
#include <cuda_runtime.h>
#include <cuda_bf16.h>
#include <cstdint>

#define M_MATCH 5000
#define TOT     10000
#define CF      128
#define CC      256
#define WW      25
#define LCELLS  4800
#define HFD     240
#define WFD     320
#define CHW     (CF * HFD * WFD)

typedef unsigned long long ull;

__device__ float g_t[TOT * CF];
__device__ float g_Wc[CC * CF];
__device__ float g_bc[CF];

__device__ __forceinline__ uint32_t smem_u32(const void* p) {
    uint32_t a;
    asm("{ .reg .u64 t; cvta.to.shared.u64 t, %1; cvt.u32.u64 %0, t; }" : "=r"(a) : "l"(p));
    return a;
}

#define LDSM_X4(r0, r1, r2, r3, addr)                                          \
    asm volatile("ldmatrix.sync.aligned.m8n8.x4.shared.b16 {%0,%1,%2,%3}, [%4];" \
        : "=r"(r0), "=r"(r1), "=r"(r2), "=r"(r3) : "r"(addr))

#define MMA16816(d, a0, a1, a2, a3, b0, b1)                                    \
    asm volatile("mma.sync.aligned.m16n8k16.row.col.f32.bf16.bf16.f32 "        \
        "{%0,%1,%2,%3}, {%4,%5,%6,%7}, {%8,%9}, {%0,%1,%2,%3};"                \
        : "+f"((d)[0]), "+f"((d)[1]), "+f"((d)[2]), "+f"((d)[3])               \
        : "r"(a0), "r"(a1), "r"(a2), "r"(a3), "r"(b0), "r"(b1))

#define CP_ASYNC4(dst, src, sz)                                                \
    asm volatile("cp.async.ca.shared.global [%0], [%1], 4, %2;"                \
        :: "r"(dst), "l"(src), "r"(sz) : "memory")
#define CP_COMMIT() asm volatile("cp.async.commit_group;" ::: "memory")
#define CP_WAIT0()  asm volatile("cp.async.wait_group 0;" ::: "memory")

__global__ void warmup_kernel() {}

// ---------------------------------------------------------------------------
// Kernel 0: Wc[c][o] = sum_j Wd[j][c]*W2[o][j];  bc = W2@bd + bm
// ---------------------------------------------------------------------------
__global__ void __launch_bounds__(128)
wc_kernel(const float* __restrict__ Wd, const float* __restrict__ bd,
          const float* __restrict__ Wm, const float* __restrict__ bm)
{
    extern __shared__ float w2T[];   // [j][129]
    const int tid = threadIdx.x;
    const int c = blockIdx.x;

    for (int it = 0; it < 128; it++)
        w2T[tid * 129 + it] = Wm[it * 256 + 128 + tid];   // w2T[j=tid][o=it]
    __syncthreads();

    float a0 = 0.f, a1 = 0.f;
    #pragma unroll 4
    for (int j = 0; j < 128; j++) {
        float w2 = w2T[j * 129 + tid];
        a0 += __ldg(&Wd[j * 256 + c])       * w2;
        a1 += __ldg(&Wd[j * 256 + c + 128]) * w2;
    }
    g_Wc[(size_t)c * 128 + tid]         = a0;
    g_Wc[(size_t)(c + 128) * 128 + tid] = a1;

    if (blockIdx.x == 0) {
        float acc = bm[tid];
        #pragma unroll 4
        for (int j = 0; j < 128; j++)
            acc += w2T[j * 129 + tid] * __ldg(&bd[j]);
        g_bc[tid] = acc;
    }
}

// ---------------------------------------------------------------------------
// Kernel 1: t = gather(feat_c) @ Wc + bc.  32-row tiles, 313 blocks, occ 2.
// ---------------------------------------------------------------------------
#define PTILE 32
#define NPTILES ((TOT + PTILE - 1) / PTILE)   // 313

__global__ void __launch_bounds__(256, 2)
proj_kernel(const float* __restrict__ feat_c0, const float* __restrict__ feat_c1,
            const int* __restrict__ b_ids, const int* __restrict__ i_ids,
            const int* __restrict__ j_ids)
{
    extern __shared__ char sraw[];
    float* A   = (float*)sraw;                       // [32][64]
    float* Wcs = (float*)(sraw + 8192);              // [64][128]
    const float** srow = (const float**)(sraw + 8192 + 32768);

    const int tid = threadIdx.x;
    const int tile = blockIdx.x;
    const int og = tid & 15, rg = tid >> 4;
    const int o0 = og * 8;

    if (tid < PTILE) {
        int m = tile * PTILE + tid;
        const float* p = nullptr;
        if (m < TOT) {
            int mm = (m < M_MATCH) ? m : m - M_MATCH;
            int b  = b_ids[mm];
            int l  = (m < M_MATCH) ? i_ids[mm] : j_ids[mm];
            p = ((m < M_MATCH) ? feat_c0 : feat_c1) + ((size_t)b * LCELLS + l) * CC;
        }
        srow[tid] = p;
    }

    float acc[2][8];
    {
        float4 bA = *(const float4*)&g_bc[o0];
        float4 bB = *(const float4*)&g_bc[o0 + 4];
        #pragma unroll
        for (int j = 0; j < 2; j++) {
            acc[j][0] = bA.x; acc[j][1] = bA.y; acc[j][2] = bA.z; acc[j][3] = bA.w;
            acc[j][4] = bB.x; acc[j][5] = bB.y; acc[j][6] = bB.z; acc[j][7] = bB.w;
        }
    }
    __syncthreads();

    for (int kc = 0; kc < 256; kc += 64) {
        for (int e = tid; e < 32 * 64; e += 256) {
            const float* p = srow[e >> 6];
            A[e] = p ? __ldg(p + kc + (e & 63)) : 0.f;
        }
        for (int e = tid; e < 64 * 128; e += 256)
            Wcs[e] = g_Wc[(size_t)(kc + (e >> 7)) * 128 + (e & 127)];
        __syncthreads();

        #pragma unroll 2
        for (int k = 0; k < 64; k += 4) {
            float4 fv[2];
            #pragma unroll
            for (int j = 0; j < 2; j++)
                fv[j] = *(const float4*)&A[(rg + 16 * j) * 64 + k];
            #define PSTEP(kk, COMP)                                            \
            {                                                                  \
                float4 wA = *(const float4*)&Wcs[(k + kk) * 128 + o0];         \
                float4 wB = *(const float4*)&Wcs[(k + kk) * 128 + o0 + 4];     \
                _Pragma("unroll")                                              \
                for (int j = 0; j < 2; j++) {                                  \
                    float a = fv[j].COMP;                                      \
                    acc[j][0] += a * wA.x; acc[j][1] += a * wA.y;              \
                    acc[j][2] += a * wA.z; acc[j][3] += a * wA.w;              \
                    acc[j][4] += a * wB.x; acc[j][5] += a * wB.y;              \
                    acc[j][6] += a * wB.z; acc[j][7] += a * wB.w;              \
                }                                                              \
            }
            PSTEP(0, x) PSTEP(1, y) PSTEP(2, z) PSTEP(3, w)
            #undef PSTEP
        }
        __syncthreads();
    }

    #pragma unroll
    for (int j = 0; j < 2; j++) {
        int m = tile * PTILE + rg + 16 * j;
        if (m < TOT) {
            float* dst = &g_t[(size_t)m * CF + o0];
            *(float4*)dst       = make_float4(acc[j][0], acc[j][1], acc[j][2], acc[j][3]);
            *(float4*)(dst + 4) = make_float4(acc[j][4], acc[j][5], acc[j][6], acc[j][7]);
        }
    }
}

// ---------------------------------------------------------------------------
// Kernel 2: fine — coalesced incremental gather + HMMA.
// This round: Bh reused across terms 1&3 (8 LDSM/ks, was 10); uint4 convert.
// ---------------------------------------------------------------------------
#define APITCH   136
#define ABYTES   (128 * APITCH * 2)
#define OFF_AH   0
#define OFF_AL   34816
#define OFF_BH   69632
#define OFF_BL   104448
#define OFF_STG  139264
#define OFF_TS   204800
#define OFF_NSFB 209920
#define OFF_NSL  209960
#define SMEM_FINE 210048

__device__ __forceinline__ void decode_flat(unsigned flat, int& pos, int& p80,
                                            int& row, int& col, int& off)
{
    unsigned ch = flat / 120000u;
    unsigned r1 = flat - ch * 120000u;
    unsigned kk = r1 / 4800u;
    unsigned pp = r1 - kk * 4800u;
    int kh = (int)(kk / 5u);
    int kw = (int)(kk - 5u * (unsigned)kh);
    unsigned oh = pp / 80u;
    p80 = (int)(pp - 80u * oh);
    pos = (int)pp;
    row = (int)oh * 4 + kh - 2;
    col = p80 * 4 + kw - 2;
    off = (int)ch * 76800 + row * 320 + col;
}

__device__ __forceinline__ void issue_tile(
    uint32_t stg_sm, uint32_t tdst_sm,
    const int* nsl, const ull* nsfb, int nxt5, int tid, int wid, int lane)
{
    #pragma unroll
    for (int rr = 0; rr < 8; rr++) {
        const int r = wid * 8 + rr;
        uint32_t dst = stg_sm + (uint32_t)(r * 128 + lane) * 4;
        if (r < 125) {
            const int mi = r / 25;
            const int w  = r - mi * 25;
            const float* fb = (const float*)nsfb[mi];
            unsigned flat = (unsigned)nsl[mi] * 3200u + (unsigned)(w * 128 + lane);
            int pos, p80, row, col, off;
            decode_flat(flat, pos, p80, row, col, off);
            #pragma unroll
            for (int q = 0; q < 4; q++) {
                const bool valid = ((row | col) >= 0);
                const float* src = valid ? (fb + off) : fb;
                CP_ASYNC4(dst, src, valid ? 4u : 0u);
                dst += 128;
                if (q < 3) {
                    flat += 32; pos += 32; p80 += 32; col += 128; off += 128;
                    if (pos >= 4800) {
                        decode_flat(flat, pos, p80, row, col, off);
                    } else if (p80 >= 80) {
                        p80 -= 80; row += 4; col -= 320; off += 960;
                    }
                }
            }
        } else {
            const float* fb = (const float*)nsfb[0];
            #pragma unroll
            for (int q = 0; q < 4; q++) {
                CP_ASYNC4(dst, fb, 0u);
                dst += 128;
            }
        }
    }
    #pragma unroll
    for (int e2 = tid; e2 < 640; e2 += 512) {
        const float* src = &g_t[(size_t)(nxt5 + (e2 >> 7)) * CF + (e2 & 127)];
        CP_ASYNC4(tdst_sm + (uint32_t)e2 * 4, src, 4u);
    }
    CP_COMMIT();
}

__global__ void __launch_bounds__(512, 1)
fine_kernel(const float* __restrict__ feat_f0, const float* __restrict__ feat_f1,
            const int* __restrict__ b_ids, const int* __restrict__ i_ids,
            const int* __restrict__ j_ids,
            const float* __restrict__ Wm, float* __restrict__ out)
{
    extern __shared__ char sraw[];
    char* Ah = sraw + OFF_AH;
    char* Al = sraw + OFF_AL;
    char* Bh = sraw + OFF_BH;
    char* Bl = sraw + OFF_BL;
    float* stg = (float*)(sraw + OFF_STG);
    float* ts0 = (float*)(sraw + OFF_TS);
    ull*   nsfb = (ull*)(sraw + OFF_NSFB);
    int*   nsl  = (int*)(sraw + OFF_NSL);

    const uint32_t sAh = smem_u32(Ah);
    const uint32_t sAl = smem_u32(Al);
    const uint32_t sBh = smem_u32(Bh);
    const uint32_t sBl = smem_u32(Bl);
    const uint32_t sStg = smem_u32(stg);
    const uint32_t sTs  = smem_u32(ts0);

    const int tid  = threadIdx.x;
    const int wid  = tid >> 5;
    const int lane = tid & 31;
    const int grid = gridDim.x;

    for (int e2 = tid; e2 < 8192; e2 += 512) {
        int o = e2 >> 6;
        int c = (e2 & 63) * 2;
        float v0 = Wm[o * 256 + c];
        float v1 = Wm[o * 256 + c + 1];
        __nv_bfloat16 h0 = __float2bfloat16(v0);
        __nv_bfloat16 h1 = __float2bfloat16(v1);
        __nv_bfloat16 l0 = __float2bfloat16(v0 - __bfloat162float(h0));
        __nv_bfloat16 l1 = __float2bfloat16(v1 - __bfloat162float(h1));
        __nv_bfloat162 hp, lp; hp.x = h0; hp.y = h1; lp.x = l0; lp.y = l1;
        *(uint32_t*)(Bh + o * 272 + c * 2) = *(uint32_t*)&hp;
        *(uint32_t*)(Bl + o * 272 + c * 2) = *(uint32_t*)&lp;
    }

    const int mbase = (wid & 3) * 32;
    const int nbase = (wid >> 2) * 32;
    const uint32_t aRow  = (uint32_t)(mbase + (lane & 15));
    const uint32_t aColB = (uint32_t)((lane >> 4) * 16);
    const uint32_t bRow  = (uint32_t)(nbase + (lane & 7) + ((lane >> 4) << 3));
    const uint32_t bColB = (uint32_t)(((lane >> 3) & 1) * 16);

    const int rl = lane >> 2;
    const int cl = 2 * (lane & 3);
    int  rcst[4], rmi[4];
    bool rvld[4];
    #pragma unroll
    for (int jj = 0; jj < 4; jj++) {
        int r = mbase + 8 * jj + rl;
        rvld[jj] = (r < 125);
        int mi = r / 25;
        int w  = r - mi * 25;
        rmi[jj]  = mi;
        rcst[jj] = mi * 3200 + w * 128;
    }

    if (tid < 5) {
        int m  = (int)blockIdx.x * 5 + tid;
        int mm = (m < M_MATCH) ? m : m - M_MATCH;
        int b  = b_ids[mm];
        nsl[tid]  = (m < M_MATCH) ? i_ids[mm] : j_ids[mm];
        nsfb[tid] = (ull)(((m < M_MATCH) ? feat_f0 : feat_f1) + (size_t)b * CHW);
    }
    __syncthreads();
    issue_tile(sStg, sTs, nsl, nsfb, (int)blockIdx.x * 5, tid, wid, lane);

    int buf = 0;

    for (int tile = blockIdx.x; tile < 2000; tile += grid) {
        const int nxt = tile + grid;

        CP_WAIT0();
        __syncthreads();

        if (tid < 5 && nxt < 2000) {
            int m  = nxt * 5 + tid;
            int mm = (m < M_MATCH) ? m : m - M_MATCH;
            int b  = b_ids[mm];
            nsl[tid]  = (m < M_MATCH) ? i_ids[mm] : j_ids[mm];
            nsfb[tid] = (ull)(((m < M_MATCH) ? feat_f0 : feat_f1) + (size_t)b * CHW);
        }

        // convert stage -> Ah/Al: 4 elems/thread/iter (LDS.128 + 2x STS.64)
        #pragma unroll 4
        for (int i = 0; i < 8; i++) {
            int e4 = tid + (i << 9);              // 0..4095, 4 elems each
            int r = e4 >> 5, cq = e4 & 31;        // cq*4 = c base
            uint4 u = *(const uint4*)&stg[r * 128 + cq * 4];
            uint32_t h0 = u.x & 0xFFFF0000u;
            uint32_t h1 = u.y & 0xFFFF0000u;
            uint32_t h2 = u.z & 0xFFFF0000u;
            uint32_t h3 = u.w & 0xFFFF0000u;
            float l0 = __uint_as_float(u.x) - __uint_as_float(h0);
            float l1 = __uint_as_float(u.y) - __uint_as_float(h1);
            float l2 = __uint_as_float(u.z) - __uint_as_float(h2);
            float l3 = __uint_as_float(u.w) - __uint_as_float(h3);
            uint2 hp, lp;
            hp.x = __byte_perm(u.x, u.y, 0x7632);
            hp.y = __byte_perm(u.z, u.w, 0x7632);
            lp.x = __byte_perm(__float_as_uint(l0), __float_as_uint(l1), 0x7632);
            lp.y = __byte_perm(__float_as_uint(l2), __float_as_uint(l3), 0x7632);
            *(uint2*)(Ah + r * 272 + cq * 8) = hp;
            *(uint2*)(Al + r * 272 + cq * 8) = lp;
        }
        __syncthreads();

        if (nxt < 2000)
            issue_tile(sStg, sTs + (uint32_t)(buf ^ 1) * 2560, nsl, nsfb, nxt * 5,
                       tid, wid, lane);

        // ---- MMA: reordered terms, Bh loaded once per ks (8 LDSM/ks) ----
        float acc[2][4][4];
        #pragma unroll
        for (int i = 0; i < 2; i++)
            #pragma unroll
            for (int nb = 0; nb < 4; nb++) {
                acc[i][nb][0] = 0.f; acc[i][nb][1] = 0.f;
                acc[i][nb][2] = 0.f; acc[i][nb][3] = 0.f;
            }

        #pragma unroll 1
        for (int ks = 0; ks < 8; ks++) {
            const uint32_t kb = (uint32_t)(ks * 32);
            uint32_t ah0_0, ah0_1, ah0_2, ah0_3, ah1_0, ah1_1, ah1_2, ah1_3;
            uint32_t al0_0, al0_1, al0_2, al0_3, al1_0, al1_1, al1_2, al1_3;
            uint32_t bfr[4][2];

            // load Ah + Bh
            LDSM_X4(ah0_0, ah0_1, ah0_2, ah0_3, sAh + aRow * 272 + kb + aColB);
            LDSM_X4(ah1_0, ah1_1, ah1_2, ah1_3, sAh + (aRow + 16) * 272 + kb + aColB);
            #pragma unroll
            for (int bb = 0; bb < 2; bb++)
                LDSM_X4(bfr[2*bb][0], bfr[2*bb][1], bfr[2*bb+1][0], bfr[2*bb+1][1],
                        sBh + (bRow + bb * 16) * 272 + kb + bColB);
            // term 1: Ah * Bh
            #pragma unroll
            for (int nb = 0; nb < 4; nb++) {
                MMA16816(acc[0][nb], ah0_0, ah0_1, ah0_2, ah0_3, bfr[nb][0], bfr[nb][1]);
                MMA16816(acc[1][nb], ah1_0, ah1_1, ah1_2, ah1_3, bfr[nb][0], bfr[nb][1]);
            }
            // load Al; term 3: Al * Bh (Bh reused)
            LDSM_X4(al0_0, al0_1, al0_2, al0_3, sAl + aRow * 272 + kb + aColB);
            LDSM_X4(al1_0, al1_1, al1_2, al1_3, sAl + (aRow + 16) * 272 + kb + aColB);
            #pragma unroll
            for (int nb = 0; nb < 4; nb++) {
                MMA16816(acc[0][nb], al0_0, al0_1, al0_2, al0_3, bfr[nb][0], bfr[nb][1]);
                MMA16816(acc[1][nb], al1_0, al1_1, al1_2, al1_3, bfr[nb][0], bfr[nb][1]);
            }
            // load Bl; term 2: Ah * Bl (Ah reused)
            #pragma unroll
            for (int bb = 0; bb < 2; bb++)
                LDSM_X4(bfr[2*bb][0], bfr[2*bb][1], bfr[2*bb+1][0], bfr[2*bb+1][1],
                        sBl + (bRow + bb * 16) * 272 + kb + bColB);
            #pragma unroll
            for (int nb = 0; nb < 4; nb++) {
                MMA16816(acc[0][nb], ah0_0, ah0_1, ah0_2, ah0_3, bfr[nb][0], bfr[nb][1]);
                MMA16816(acc[1][nb], ah1_0, ah1_1, ah1_2, ah1_3, bfr[nb][0], bfr[nb][1]);
            }
        }

        // ---- epilogue ----
        {
            const float* tsp = ts0 + buf * 640;
            float* outb = out + (size_t)tile * 16000;
            #pragma unroll
            for (int i = 0; i < 2; i++) {
                const int j0 = 2 * i, j1 = 2 * i + 1;
                #pragma unroll
                for (int nb = 0; nb < 4; nb++) {
                    int col = nbase + nb * 8 + cl;
                    if (rvld[j0]) {
                        float2 o2;
                        o2.x = acc[i][nb][0] + tsp[rmi[j0] * 128 + col];
                        o2.y = acc[i][nb][1] + tsp[rmi[j0] * 128 + col + 1];
                        *(float2*)&outb[rcst[j0] + col] = o2;
                    }
                    if (rvld[j1]) {
                        float2 o2;
                        o2.x = acc[i][nb][2] + tsp[rmi[j1] * 128 + col];
                        o2.y = acc[i][nb][3] + tsp[rmi[j1] * 128 + col + 1];
                        *(float2*)&outb[rcst[j1] + col] = o2;
                    }
                }
            }
        }
        buf ^= 1;
        __syncthreads();
    }
}

// ---------------------------------------------------------------------------
extern "C" void kernel_launch(void* const* d_in, const int* in_sizes, int n_in,
                              void* d_out, int out_size)
{
    (void)in_sizes; (void)n_in; (void)out_size;
    const float* feat_f0 = (const float*)d_in[0];
    const float* feat_f1 = (const float*)d_in[1];
    const float* feat_c0 = (const float*)d_in[2];
    const float* feat_c1 = (const float*)d_in[3];
    const int*   b_ids   = (const int*)d_in[4];
    const int*   i_ids   = (const int*)d_in[5];
    const int*   j_ids   = (const int*)d_in[6];
    const float* Wd      = (const float*)d_in[7];
    const float* bd      = (const float*)d_in[8];
    const float* Wm      = (const float*)d_in[9];
    const float* bm      = (const float*)d_in[10];
    float* out = (float*)d_out;

    const size_t smemW = 128 * 129 * sizeof(float);
    const size_t smemP = 8192 + 32768 + PTILE * sizeof(float*);
    const size_t smemF = SMEM_FINE;

    cudaFuncSetAttribute(wc_kernel,   cudaFuncAttributeMaxDynamicSharedMemorySize, (int)smemW);
    cudaFuncSetAttribute(proj_kernel, cudaFuncAttributeMaxDynamicSharedMemorySize, (int)smemP);
    cudaFuncSetAttribute(fine_kernel, cudaFuncAttributeMaxDynamicSharedMemorySize, (int)smemF);

    warmup_kernel<<<1, 32>>>();
    wc_kernel<<<128, 128, smemW>>>(Wd, bd, Wm, bm);
    proj_kernel<<<NPTILES, 256, smemP>>>(feat_c0, feat_c1, b_ids, i_ids, j_ids);
    fine_kernel<<<148, 512, smemF>>>(feat_f0, feat_f1, b_ids, i_ids, j_ids, Wm, out);
}

// round 11
// speedup vs baseline: 2.0161x; 1.0401x over previous
#include <cuda_runtime.h>
#include <cuda_bf16.h>
#include <cstdint>

#define M_MATCH 5000
#define TOT     10000
#define CF      128
#define CC      256
#define WW      25
#define LCELLS  4800
#define HFD     240
#define WFD     320
#define CHW     (CF * HFD * WFD)
#define G_TOTAL 250000              // 2M * 25 window rows
#define TILES   3907                // ceil(250000/64)

typedef unsigned long long ull;

__device__ float g_t[TOT * CF];
__device__ float g_Wc[CC * CF];
__device__ float g_bc[CF];

__device__ __forceinline__ uint32_t smem_u32(const void* p) {
    uint32_t a;
    asm("{ .reg .u64 t; cvta.to.shared.u64 t, %1; cvt.u32.u64 %0, t; }" : "=r"(a) : "l"(p));
    return a;
}

#define LDSM_X4(r0, r1, r2, r3, addr)                                          \
    asm volatile("ldmatrix.sync.aligned.m8n8.x4.shared.b16 {%0,%1,%2,%3}, [%4];" \
        : "=r"(r0), "=r"(r1), "=r"(r2), "=r"(r3) : "r"(addr))

#define MMA16816(d, a0, a1, a2, a3, b0, b1)                                    \
    asm volatile("mma.sync.aligned.m16n8k16.row.col.f32.bf16.bf16.f32 "        \
        "{%0,%1,%2,%3}, {%4,%5,%6,%7}, {%8,%9}, {%0,%1,%2,%3};"                \
        : "+f"((d)[0]), "+f"((d)[1]), "+f"((d)[2]), "+f"((d)[3])               \
        : "r"(a0), "r"(a1), "r"(a2), "r"(a3), "r"(b0), "r"(b1))

#define CP_ASYNC4(dst, src, sz)                                                \
    asm volatile("cp.async.ca.shared.global [%0], [%1], 4, %2;"                \
        :: "r"(dst), "l"(src), "r"(sz) : "memory")
#define CP_COMMIT() asm volatile("cp.async.commit_group;" ::: "memory")
#define CP_WAIT1()  asm volatile("cp.async.wait_group 1;" ::: "memory")

__global__ void warmup_kernel() {}

// ---------------------------------------------------------------------------
// Kernel 0: Wc[c][o] = sum_j Wd[j][c]*W2[o][j];  bc = W2@bd + bm
// ---------------------------------------------------------------------------
__global__ void __launch_bounds__(128)
wc_kernel(const float* __restrict__ Wd, const float* __restrict__ bd,
          const float* __restrict__ Wm, const float* __restrict__ bm)
{
    extern __shared__ float w2T[];   // [j][129]
    const int tid = threadIdx.x;
    const int c = blockIdx.x;

    for (int it = 0; it < 128; it++)
        w2T[tid * 129 + it] = Wm[it * 256 + 128 + tid];
    __syncthreads();

    float a0 = 0.f, a1 = 0.f;
    #pragma unroll 4
    for (int j = 0; j < 128; j++) {
        float w2 = w2T[j * 129 + tid];
        a0 += __ldg(&Wd[j * 256 + c])       * w2;
        a1 += __ldg(&Wd[j * 256 + c + 128]) * w2;
    }
    g_Wc[(size_t)c * 128 + tid]         = a0;
    g_Wc[(size_t)(c + 128) * 128 + tid] = a1;

    if (blockIdx.x == 0) {
        float acc = bm[tid];
        #pragma unroll 4
        for (int j = 0; j < 128; j++)
            acc += w2T[j * 129 + tid] * __ldg(&bd[j]);
        g_bc[tid] = acc;
    }
}

// ---------------------------------------------------------------------------
// Kernel 1: t = gather(feat_c) @ Wc + bc.  (unchanged, verified)
// ---------------------------------------------------------------------------
#define PTILE 32
#define NPTILES ((TOT + PTILE - 1) / PTILE)

__global__ void __launch_bounds__(256, 2)
proj_kernel(const float* __restrict__ feat_c0, const float* __restrict__ feat_c1,
            const int* __restrict__ b_ids, const int* __restrict__ i_ids,
            const int* __restrict__ j_ids)
{
    extern __shared__ char sraw[];
    float* A   = (float*)sraw;
    float* Wcs = (float*)(sraw + 8192);
    const float** srow = (const float**)(sraw + 8192 + 32768);

    const int tid = threadIdx.x;
    const int tile = blockIdx.x;
    const int og = tid & 15, rg = tid >> 4;
    const int o0 = og * 8;

    if (tid < PTILE) {
        int m = tile * PTILE + tid;
        const float* p = nullptr;
        if (m < TOT) {
            int mm = (m < M_MATCH) ? m : m - M_MATCH;
            int b  = b_ids[mm];
            int l  = (m < M_MATCH) ? i_ids[mm] : j_ids[mm];
            p = ((m < M_MATCH) ? feat_c0 : feat_c1) + ((size_t)b * LCELLS + l) * CC;
        }
        srow[tid] = p;
    }

    float acc[2][8];
    {
        float4 bA = *(const float4*)&g_bc[o0];
        float4 bB = *(const float4*)&g_bc[o0 + 4];
        #pragma unroll
        for (int j = 0; j < 2; j++) {
            acc[j][0] = bA.x; acc[j][1] = bA.y; acc[j][2] = bA.z; acc[j][3] = bA.w;
            acc[j][4] = bB.x; acc[j][5] = bB.y; acc[j][6] = bB.z; acc[j][7] = bB.w;
        }
    }
    __syncthreads();

    for (int kc = 0; kc < 256; kc += 64) {
        for (int e = tid; e < 32 * 64; e += 256) {
            const float* p = srow[e >> 6];
            A[e] = p ? __ldg(p + kc + (e & 63)) : 0.f;
        }
        for (int e = tid; e < 64 * 128; e += 256)
            Wcs[e] = g_Wc[(size_t)(kc + (e >> 7)) * 128 + (e & 127)];
        __syncthreads();

        #pragma unroll 2
        for (int k = 0; k < 64; k += 4) {
            float4 fv[2];
            #pragma unroll
            for (int j = 0; j < 2; j++)
                fv[j] = *(const float4*)&A[(rg + 16 * j) * 64 + k];
            #define PSTEP(kk, COMP)                                            \
            {                                                                  \
                float4 wA = *(const float4*)&Wcs[(k + kk) * 128 + o0];         \
                float4 wB = *(const float4*)&Wcs[(k + kk) * 128 + o0 + 4];     \
                _Pragma("unroll")                                              \
                for (int j = 0; j < 2; j++) {                                  \
                    float a = fv[j].COMP;                                      \
                    acc[j][0] += a * wA.x; acc[j][1] += a * wA.y;              \
                    acc[j][2] += a * wA.z; acc[j][3] += a * wA.w;              \
                    acc[j][4] += a * wB.x; acc[j][5] += a * wB.y;              \
                    acc[j][6] += a * wB.z; acc[j][7] += a * wB.w;              \
                }                                                              \
            }
            PSTEP(0, x) PSTEP(1, y) PSTEP(2, z) PSTEP(3, w)
            #undef PSTEP
        }
        __syncthreads();
    }

    #pragma unroll
    for (int j = 0; j < 2; j++) {
        int m = tile * PTILE + rg + 16 * j;
        if (m < TOT) {
            float* dst = &g_t[(size_t)m * CF + o0];
            *(float4*)dst       = make_float4(acc[j][0], acc[j][1], acc[j][2], acc[j][3]);
            *(float4*)(dst + 4) = make_float4(acc[j][4], acc[j][5], acc[j][6], acc[j][7]);
        }
    }
}

// ---------------------------------------------------------------------------
// Kernel 2: fine — 64-row dense tiles over global row g, depth-2 cp.async
// pipeline (wait_group 1), HMMA 3-term hi/lo.
// ---------------------------------------------------------------------------
#define OFF_BH   0                      // 128 x 272B  = 34816
#define OFF_BL   34816
#define OFF_AH   69632                  // 64 x 272B   = 17408
#define OFF_AL   87040
#define OFF_STG  104448                 // 2 x 32768
#define OFF_TS   169984                 // 3 x 2048
#define SMEM_FINE 176128

__device__ __forceinline__ void decode_flat(unsigned flat, int& pos, int& p80,
                                            int& row, int& col, int& off)
{
    unsigned ch = flat / 120000u;
    unsigned r1 = flat - ch * 120000u;
    unsigned kk = r1 / 4800u;
    unsigned pp = r1 - kk * 4800u;
    int kh = (int)(kk / 5u);
    int kw = (int)(kk - 5u * (unsigned)kh);
    unsigned oh = pp / 80u;
    p80 = (int)(pp - 80u * oh);
    pos = (int)pp;
    row = (int)oh * 4 + kh - 2;
    col = p80 * 4 + kw - 2;
    off = (int)ch * 76800 + row * 320 + col;
}

// Issue gather + t-prefetch for tile t2 into the given staging/ts slots.
// ALWAYS commits a group (empty when t2 >= TILES) to keep wait_group counts.
__device__ __forceinline__ void issue_tile(
    uint32_t stg_sm, uint32_t ts_sm, int t2,
    const float* __restrict__ f0, const float* __restrict__ f1,
    const int* __restrict__ b_ids, const int* __restrict__ i_ids,
    const int* __restrict__ j_ids,
    int tid, int wid, int lane)
{
    if (t2 < TILES) {
        const int g0 = t2 * 64;
        #pragma unroll
        for (int rr = 0; rr < 4; rr++) {
            const int r = wid * 4 + rr;
            const int g = g0 + r;
            uint32_t dst = stg_sm + (uint32_t)(r * 128 + lane) * 4;
            if (g < G_TOTAL) {
                const int m  = g / 25;
                const int w  = g - m * 25;
                const int mm = (m < M_MATCH) ? m : m - M_MATCH;
                const int b  = __ldg(&b_ids[mm]);
                const int l  = (m < M_MATCH) ? __ldg(&i_ids[mm]) : __ldg(&j_ids[mm]);
                const float* fb = ((m < M_MATCH) ? f0 : f1) + (size_t)b * CHW;
                unsigned flat = (unsigned)l * 3200u + (unsigned)(w * 128 + lane);
                int pos, p80, row, col, off;
                decode_flat(flat, pos, p80, row, col, off);
                #pragma unroll
                for (int q = 0; q < 4; q++) {
                    const bool valid = ((row | col) >= 0);
                    const float* src = valid ? (fb + off) : fb;
                    CP_ASYNC4(dst, src, valid ? 4u : 0u);
                    dst += 128;
                    if (q < 3) {
                        flat += 32; pos += 32; p80 += 32; col += 128; off += 128;
                        if (pos >= 4800) {
                            decode_flat(flat, pos, p80, row, col, off);
                        } else if (p80 >= 80) {
                            p80 -= 80; row += 4; col -= 320; off += 960;
                        }
                    }
                }
            } else {
                const float* fb = f0;
                #pragma unroll
                for (int q = 0; q < 4; q++) { CP_ASYNC4(dst, fb, 0u); dst += 128; }
            }
        }
        // t prefetch: 4 matches starting at mb2 (512 floats, 512 threads)
        const int mb2 = g0 / 25;
        const int m2 = mb2 + (tid >> 7);
        const float* src = (m2 < TOT) ? &g_t[(size_t)m2 * CF + (tid & 127)] : &g_t[0];
        CP_ASYNC4(ts_sm + (uint32_t)tid * 4, src, (m2 < TOT) ? 4u : 0u);
    }
    CP_COMMIT();
}

__global__ void __launch_bounds__(512, 1)
fine_kernel(const float* __restrict__ feat_f0, const float* __restrict__ feat_f1,
            const int* __restrict__ b_ids, const int* __restrict__ i_ids,
            const int* __restrict__ j_ids,
            const float* __restrict__ Wm, float* __restrict__ out)
{
    extern __shared__ char sraw[];
    char* Bh = sraw + OFF_BH;
    char* Bl = sraw + OFF_BL;
    char* Ah = sraw + OFF_AH;
    char* Al = sraw + OFF_AL;
    float* stg = (float*)(sraw + OFF_STG);
    float* ts0 = (float*)(sraw + OFF_TS);

    const uint32_t sBh = smem_u32(Bh);
    const uint32_t sBl = smem_u32(Bl);
    const uint32_t sAh = smem_u32(Ah);
    const uint32_t sAl = smem_u32(Al);
    const uint32_t sStg = smem_u32(stg);
    const uint32_t sTs  = smem_u32(ts0);

    const int tid  = threadIdx.x;
    const int wid  = tid >> 5;
    const int lane = tid & 31;
    const int grid = gridDim.x;

    // B prep: W1 = merge_w[:, :128], hi/lo split, [o][c] pitch 272B
    for (int e2 = tid; e2 < 8192; e2 += 512) {
        int o = e2 >> 6;
        int c = (e2 & 63) * 2;
        float v0 = Wm[o * 256 + c];
        float v1 = Wm[o * 256 + c + 1];
        __nv_bfloat16 h0 = __float2bfloat16(v0);
        __nv_bfloat16 h1 = __float2bfloat16(v1);
        __nv_bfloat16 l0 = __float2bfloat16(v0 - __bfloat162float(h0));
        __nv_bfloat16 l1 = __float2bfloat16(v1 - __bfloat162float(h1));
        __nv_bfloat162 hp, lp; hp.x = h0; hp.y = h1; lp.x = l0; lp.y = l1;
        *(uint32_t*)(Bh + o * 272 + c * 2) = *(uint32_t*)&hp;
        *(uint32_t*)(Bl + o * 272 + c * 2) = *(uint32_t*)&lp;
    }
    __syncthreads();

    // warp grid: rg (2 row groups of 32) x cg (8 col groups of 16)
    const int rg = wid & 1;
    const int cg = wid >> 1;
    const int rbase = rg * 32;
    const int cbase = cg * 16;
    const uint32_t aRow  = (uint32_t)(rbase + (lane & 15));
    const uint32_t aColB = (uint32_t)((lane >> 4) * 16);
    const uint32_t bRow  = (uint32_t)(cbase + (lane & 7) + ((lane >> 4) << 3));
    const uint32_t bColB = (uint32_t)(((lane >> 3) & 1) * 16);
    const int rl = lane >> 2;
    const int cl = 2 * (lane & 3);

    // prologue: depth-2 pipeline fill
    issue_tile(sStg,         sTs,        (int)blockIdx.x,
               feat_f0, feat_f1, b_ids, i_ids, j_ids, tid, wid, lane);
    issue_tile(sStg + 32768, sTs + 2048, (int)blockIdx.x + grid,
               feat_f0, feat_f1, b_ids, i_ids, j_ids, tid, wid, lane);

    int i = 0;
    for (int tile = blockIdx.x; tile < TILES; tile += grid, i++) {
        CP_WAIT1();                    // group for THIS tile complete
        __syncthreads();

        const uint32_t slot = (uint32_t)(i & 1) * 32768;
        const float* stgp = stg + (i & 1) * 8192;

        // convert stg -> Ah/Al (truncation hi + residual lo, PRMT pack)
        #pragma unroll
        for (int it = 0; it < 4; it++) {
            int e4 = tid + (it << 9);             // 0..2047, 4 elems each
            int r = e4 >> 5, cq = e4 & 31;
            uint4 u = *(const uint4*)&stgp[r * 128 + cq * 4];
            uint32_t h0 = u.x & 0xFFFF0000u;
            uint32_t h1 = u.y & 0xFFFF0000u;
            uint32_t h2 = u.z & 0xFFFF0000u;
            uint32_t h3 = u.w & 0xFFFF0000u;
            float l0 = __uint_as_float(u.x) - __uint_as_float(h0);
            float l1 = __uint_as_float(u.y) - __uint_as_float(h1);
            float l2 = __uint_as_float(u.z) - __uint_as_float(h2);
            float l3 = __uint_as_float(u.w) - __uint_as_float(h3);
            uint2 hp, lp;
            hp.x = __byte_perm(u.x, u.y, 0x7632);
            hp.y = __byte_perm(u.z, u.w, 0x7632);
            lp.x = __byte_perm(__float_as_uint(l0), __float_as_uint(l1), 0x7632);
            lp.y = __byte_perm(__float_as_uint(l2), __float_as_uint(l3), 0x7632);
            *(uint2*)(Ah + r * 272 + cq * 8) = hp;
            *(uint2*)(Al + r * 272 + cq * 8) = lp;
        }
        __syncthreads();               // A ready; stg slot free

        // refill pipeline: tile + 2*grid into the just-freed slots
        issue_tile(sStg + slot, sTs + (uint32_t)((i + 2) % 3) * 2048,
                   tile + 2 * grid,
                   feat_f0, feat_f1, b_ids, i_ids, j_ids, tid, wid, lane);

        // ---- MMA: 3 terms x 8 k-steps, warp tile 32x16 ----
        float acc[2][2][4];
        #pragma unroll
        for (int a2 = 0; a2 < 2; a2++)
            #pragma unroll
            for (int nb = 0; nb < 2; nb++) {
                acc[a2][nb][0] = 0.f; acc[a2][nb][1] = 0.f;
                acc[a2][nb][2] = 0.f; acc[a2][nb][3] = 0.f;
            }

        #pragma unroll 1
        for (int ks = 0; ks < 8; ks++) {
            const uint32_t kb = (uint32_t)(ks * 32);
            uint32_t ah0_0, ah0_1, ah0_2, ah0_3, ah1_0, ah1_1, ah1_2, ah1_3;
            uint32_t al0_0, al0_1, al0_2, al0_3, al1_0, al1_1, al1_2, al1_3;
            uint32_t bfr[2][2];

            LDSM_X4(ah0_0, ah0_1, ah0_2, ah0_3, sAh + aRow * 272 + kb + aColB);
            LDSM_X4(ah1_0, ah1_1, ah1_2, ah1_3, sAh + (aRow + 16) * 272 + kb + aColB);
            LDSM_X4(bfr[0][0], bfr[0][1], bfr[1][0], bfr[1][1],
                    sBh + bRow * 272 + kb + bColB);
            #pragma unroll
            for (int nb = 0; nb < 2; nb++) {
                MMA16816(acc[0][nb], ah0_0, ah0_1, ah0_2, ah0_3, bfr[nb][0], bfr[nb][1]);
                MMA16816(acc[1][nb], ah1_0, ah1_1, ah1_2, ah1_3, bfr[nb][0], bfr[nb][1]);
            }
            LDSM_X4(al0_0, al0_1, al0_2, al0_3, sAl + aRow * 272 + kb + aColB);
            LDSM_X4(al1_0, al1_1, al1_2, al1_3, sAl + (aRow + 16) * 272 + kb + aColB);
            #pragma unroll
            for (int nb = 0; nb < 2; nb++) {
                MMA16816(acc[0][nb], al0_0, al0_1, al0_2, al0_3, bfr[nb][0], bfr[nb][1]);
                MMA16816(acc[1][nb], al1_0, al1_1, al1_2, al1_3, bfr[nb][0], bfr[nb][1]);
            }
            LDSM_X4(bfr[0][0], bfr[0][1], bfr[1][0], bfr[1][1],
                    sBl + bRow * 272 + kb + bColB);
            #pragma unroll
            for (int nb = 0; nb < 2; nb++) {
                MMA16816(acc[0][nb], ah0_0, ah0_1, ah0_2, ah0_3, bfr[nb][0], bfr[nb][1]);
                MMA16816(acc[1][nb], ah1_0, ah1_1, ah1_2, ah1_3, bfr[nb][0], bfr[nb][1]);
            }
        }

        // ---- epilogue: add t, dense store out[128*g + col] ----
        {
            const float* tsp = ts0 + (i % 3) * 512;
            const int g0 = tile * 64;
            const int mb = g0 / 25;
            #pragma unroll
            for (int a2 = 0; a2 < 2; a2++) {
                #pragma unroll
                for (int half = 0; half < 2; half++) {
                    const int r = rbase + a2 * 16 + half * 8 + rl;
                    const int g = g0 + r;
                    if (g < G_TOTAL) {
                        const int toff = (g / 25 - mb) * 128;
                        float* dst = out + (size_t)g * 128;
                        #pragma unroll
                        for (int nb = 0; nb < 2; nb++) {
                            const int col = cbase + nb * 8 + cl;
                            float2 o2;
                            o2.x = acc[a2][nb][2 * half]     + tsp[toff + col];
                            o2.y = acc[a2][nb][2 * half + 1] + tsp[toff + col + 1];
                            *(float2*)(dst + col) = o2;
                        }
                    }
                }
            }
        }
        __syncthreads();               // protect A / ts before next iteration
    }
}

// ---------------------------------------------------------------------------
extern "C" void kernel_launch(void* const* d_in, const int* in_sizes, int n_in,
                              void* d_out, int out_size)
{
    (void)in_sizes; (void)n_in; (void)out_size;
    const float* feat_f0 = (const float*)d_in[0];
    const float* feat_f1 = (const float*)d_in[1];
    const float* feat_c0 = (const float*)d_in[2];
    const float* feat_c1 = (const float*)d_in[3];
    const int*   b_ids   = (const int*)d_in[4];
    const int*   i_ids   = (const int*)d_in[5];
    const int*   j_ids   = (const int*)d_in[6];
    const float* Wd      = (const float*)d_in[7];
    const float* bd      = (const float*)d_in[8];
    const float* Wm      = (const float*)d_in[9];
    const float* bm      = (const float*)d_in[10];
    float* out = (float*)d_out;

    const size_t smemW = 128 * 129 * sizeof(float);
    const size_t smemP = 8192 + 32768 + PTILE * sizeof(float*);
    const size_t smemF = SMEM_FINE;

    cudaFuncSetAttribute(wc_kernel,   cudaFuncAttributeMaxDynamicSharedMemorySize, (int)smemW);
    cudaFuncSetAttribute(proj_kernel, cudaFuncAttributeMaxDynamicSharedMemorySize, (int)smemP);
    cudaFuncSetAttribute(fine_kernel, cudaFuncAttributeMaxDynamicSharedMemorySize, (int)smemF);

    warmup_kernel<<<1, 32>>>();
    wc_kernel<<<128, 128, smemW>>>(Wd, bd, Wm, bm);
    proj_kernel<<<NPTILES, 256, smemP>>>(feat_c0, feat_c1, b_ids, i_ids, j_ids);
    fine_kernel<<<148, 512, smemF>>>(feat_f0, feat_f1, b_ids, i_ids, j_ids, Wm, out);
}